// round 16
// baseline (speedup 1.0000x reference)
#include <cuda_runtime.h>
#include <cuda_bf16.h>

constexpr int kB = 8, kSeq = 8192, kCh = 256;
constexpr int kM  = kB * kSeq;          // 65536
constexpr int kN2 = 8192;               // complex FFT size (real 16384)
constexpr int kNF = 8193;               // rfft bins of 16384

__device__ __align__(128) float  g_xe [kM * kCh];   // (B,L,C)
__device__ __align__(128) float  g_xeT[kM * kCh];   // (B,C,L), preserved
__device__ __align__(128) float  g_y1 [kM * kCh];   // (B,C,L)  y1T
__device__ __align__(128) float  g_y2 [kM * kCh];   // (B,L,C), un-normalized
__device__ __align__(128) float2 g_Kf [(size_t)kCh * kNF];
__device__ __align__(128) __nv_bfloat16 g_Wh[3 * kCh * kCh];
__device__ __align__(128) __nv_bfloat16 g_Wl[3 * kCh * kCh];
__device__ float2 g_tw8 [4096];
__device__ float2 g_tw16[4097];
__device__ float  g_psum [kM * 4];
__device__ float  g_psumq[kM * 4];
__device__ float  g_mu[kM], g_rstd[kM];
__device__ unsigned g_maxxe[kB * kCh];
__device__ unsigned g_maxy [kB * kCh];

#define SWZ(i) ((i) ^ ((((i) >> 4) & 3) << 2))

__device__ __forceinline__ float2 cmul(float2 a, float2 b) {
    return make_float2(a.x * b.x - a.y * b.y, a.x * b.y + a.y * b.x);
}
__device__ __forceinline__ float2 cadd(float2 a, float2 b) {
    return make_float2(a.x + b.x, a.y + b.y);
}
__device__ __forceinline__ float2 csub(float2 a, float2 b) {
    return make_float2(a.x - b.x, a.y - b.y);
}
__device__ __forceinline__ float gelu_exact(float v) {
    return 0.5f * v * (1.0f + erff(v * 0.7071067811865476f));
}
__device__ __forceinline__ void ldsm4(unsigned* r, const void* p) {
    unsigned addr = (unsigned)__cvta_generic_to_shared(p);
    asm volatile("ldmatrix.sync.aligned.m8n8.x4.shared.b16 {%0,%1,%2,%3}, [%4];"
                 : "=r"(r[0]), "=r"(r[1]), "=r"(r[2]), "=r"(r[3]) : "r"(addr));
}
__device__ __forceinline__ void ldsm4t(unsigned* r, const void* p) {
    unsigned addr = (unsigned)__cvta_generic_to_shared(p);
    asm volatile("ldmatrix.sync.aligned.m8n8.x4.trans.shared.b16 {%0,%1,%2,%3}, [%4];"
                 : "=r"(r[0]), "=r"(r[1]), "=r"(r[2]), "=r"(r[3]) : "r"(addr));
}
__device__ __forceinline__ void mma16816(float* d, const unsigned* a, const unsigned* b) {
    asm volatile("mma.sync.aligned.m16n8k16.row.col.f32.bf16.bf16.f32 "
                 "{%0,%1,%2,%3}, {%4,%5,%6,%7}, {%8,%9}, {%0,%1,%2,%3};"
                 : "+f"(d[0]), "+f"(d[1]), "+f"(d[2]), "+f"(d[3])
                 : "r"(a[0]), "r"(a[1]), "r"(a[2]), "r"(a[3]), "r"(b[0]), "r"(b[1]));
}
__device__ __forceinline__ void cpasync16(void* smem_dst, const void* gsrc) {
    unsigned a = (unsigned)__cvta_generic_to_shared(smem_dst);
    asm volatile("cp.async.cg.shared.global [%0], [%1], 16;" :: "r"(a), "l"(gsrc));
}
#define CP_COMMIT() asm volatile("cp.async.commit_group;")
#define CP_WAIT0()  asm volatile("cp.async.wait_group 0;")

__global__ void zero_kernel() {
    int i = blockIdx.x * 256 + threadIdx.x;
    if (i < kB * kCh) { g_maxxe[i] = 0u; g_maxy[i] = 0u; }
}

__global__ void twiddle_kernel() {
    int i = blockIdx.x * 256 + threadIdx.x;
    float s, c;
    if (i < 4096) { sincospif(-2.0f * i / 8192.0f,  &s, &c); g_tw8 [i] = make_float2(c, s); }
    if (i < 4097) { sincospif(-2.0f * i / 16384.0f, &s, &c); g_tw16[i] = make_float2(c, s); }
}

__global__ void wsplit_kernel(const float* __restrict__ We, const float* __restrict__ Wf,
                              const float* __restrict__ Wd) {
    int i = blockIdx.x * 256 + threadIdx.x;
    const float* src = (blockIdx.y == 0) ? We : (blockIdx.y == 1 ? Wf : Wd);
    float v = src[i];
    __nv_bfloat16 h = __float2bfloat16(v);
    g_Wh[blockIdx.y * kCh * kCh + i] = h;
    g_Wl[blockIdx.y * kCh * kCh + i] = __float2bfloat16(v - __bfloat162float(h));
}

// Kf[c][k] = B(w)/A(w)/8192 (IIR tail underflows fp32 beyond n=8192).
__global__ __launch_bounds__(256) void kfgen_kernel(const float* __restrict__ A,
                                                    const float* __restrict__ Bp) {
    __shared__ float sA[64], sB[64];
    int c = blockIdx.y;
    if (threadIdx.x < 64)       sA[threadIdx.x]      = A [c * 64 + threadIdx.x];
    else if (threadIdx.x < 128) sB[threadIdx.x - 64] = Bp[c * 64 + threadIdx.x - 64];
    __syncthreads();
    int k = blockIdx.x * 256 + threadIdx.x;
    if (k >= kNF) return;
    float sv, cv;
    sincospif(-(float)k / 8192.0f, &sv, &cv);
    float2 w  = make_float2(cv, sv);
    float2 w2 = cmul(w, w);
    float2 ae = make_float2(sA[63], 0.f);
    float2 ao = make_float2(sA[62], 0.f);
    float2 be = make_float2(sB[62], 0.f);
    float2 bo = make_float2(sB[63], 0.f);
#pragma unroll 4
    for (int i = 31; i >= 1; --i) {
        ae = cmul(ae, w2); ae.x += sA[2 * i - 1];
        ao = cmul(ao, w2); ao.x += sA[2 * i - 2];
        be = cmul(be, w2); be.x += sB[2 * i - 2];
        bo = cmul(bo, w2); bo.x += sB[2 * i - 1];
    }
    ae = cmul(ae, w2); ae.x += 1.0f;
    float2 av = cadd(ae, cmul(w, ao));
    float2 bv = cadd(be, cmul(w, bo));
    float scl = (1.0f / 8192.0f) / (av.x * av.x + av.y * av.y);
    g_Kf[(size_t)c * kNF + k] = make_float2((bv.x * av.x + bv.y * av.y) * scl,
                                            (bv.y * av.x - bv.x * av.y) * scl);
}

// Fold the 4 per-row LN partials (fixed order -> deterministic).
__global__ void lnstats_kernel() {
    int r = blockIdx.x * 256 + threadIdx.x;
    float4 p = *reinterpret_cast<const float4*>(g_psum  + 4 * r);
    float4 q = *reinterpret_cast<const float4*>(g_psumq + 4 * r);
    float s  = (p.x + p.y) + (p.z + p.w);
    float qq = (q.x + q.y) + (q.z + q.w);
    float mu = s * (1.f / 256.f);
    g_mu[r]   = mu;
    g_rstd[r] = rsqrtf(qq * (1.f / 256.f) - mu * mu + 1e-5f);
}

// ---------------------------------------------------------------------------
// Tensor-core GEMM (3-pass bf16 split), software-pipelined.
// EPI 0: encode (x -> g_xe + g_xeT, colmax)
// EPI 1: fc     (A from y1T via ldmatrix.trans; out gelu+skip -> g_y2;
//                emits per-row LN partial sums)
// EPI 2: decode (A = LN(g_y2) applied on the fly; out -> d_out, colmax)
constexpr int kGemmSmem = 81920 + 512;

template <int EPI>
__global__ __launch_bounds__(256, 2) void gemm_kernel(const float* __restrict__ Ain,
                                                      const float* __restrict__ bias,
                                                      float* __restrict__ Cout,
                                                      const float* __restrict__ lng,
                                                      const float* __restrict__ lnb) {
    constexpr int BM = 128, BN = 128, BK = 32, LDS = 40, LDT = 136;
    extern __shared__ __align__(16) unsigned char smem_raw[];
    unsigned* red = reinterpret_cast<unsigned*>(smem_raw + 81920);
    const float* Ap = (EPI == 1) ? g_y1 : (EPI == 2 ? g_y2 : Ain);
    float*       Cp = (EPI == 0) ? g_xe : (EPI == 1 ? g_y2 : Cout);
    const __nv_bfloat16* Whp = g_Wh + EPI * kCh * kCh;
    const __nv_bfloat16* Wlp = g_Wl + EPI * kCh * kCh;
    const int m0 = blockIdx.x * BM, n0 = blockIdx.y * BN;
    const int tid = threadIdx.x, lane = tid & 31, warp = tid >> 5;
    const int wr = warp >> 1, wc = warp & 1;
    const int bB = m0 >> 13, l0m = m0 & (kSeq - 1);

    if (EPI != 1 && tid < BN) red[tid] = 0u;

    float acc[2][8][4];
#pragma unroll
    for (int mt = 0; mt < 2; ++mt)
#pragma unroll
        for (int nt = 0; nt < 8; ++nt)
#pragma unroll
            for (int r = 0; r < 4; ++r) acc[mt][nt][r] = 0.f;

    auto ldgA = [&](int kt, float4* ra) {
#pragma unroll
        for (int u = 0; u < 4; ++u) {
            int idx = u * 256 + tid;
            if (EPI == 1) {
                int ch = idx >> 5, mg = (idx & 31) * 4;
                ra[u] = *reinterpret_cast<const float4*>(
                    Ap + ((size_t)bB * kCh + kt + ch) * kSeq + l0m + mg);
            } else {
                int row = idx >> 3, c4 = (idx & 7) * 4;
                float4 v = *reinterpret_cast<const float4*>(
                    Ap + (size_t)(m0 + row) * kCh + kt + c4);
                if (EPI == 2) {      // fused LayerNorm on the A operand
                    float mu = g_mu[m0 + row], rs = g_rstd[m0 + row];
                    float4 gv = *reinterpret_cast<const float4*>(lng + kt + c4);
                    float4 bv = *reinterpret_cast<const float4*>(lnb + kt + c4);
                    v.x = (v.x - mu) * rs * gv.x + bv.x;
                    v.y = (v.y - mu) * rs * gv.y + bv.y;
                    v.z = (v.z - mu) * rs * gv.z + bv.z;
                    v.w = (v.w - mu) * rs * gv.w + bv.w;
                }
                ra[u] = v;
            }
        }
    };
    auto stA = [&](int buf, const float4* ra) {
#pragma unroll
        for (int u = 0; u < 4; ++u) {
            int idx = u * 256 + tid;
            float4 v = ra[u];
            __nv_bfloat162 h01 = __floats2bfloat162_rn(v.x, v.y);
            __nv_bfloat162 h23 = __floats2bfloat162_rn(v.z, v.w);
            __nv_bfloat162 l01 = __floats2bfloat162_rn(v.x - __low2float(h01),
                                                       v.y - __high2float(h01));
            __nv_bfloat162 l23 = __floats2bfloat162_rn(v.z - __low2float(h23),
                                                       v.w - __high2float(h23));
            uint2 hv = make_uint2(*reinterpret_cast<unsigned*>(&h01),
                                  *reinterpret_cast<unsigned*>(&h23));
            uint2 lv = make_uint2(*reinterpret_cast<unsigned*>(&l01),
                                  *reinterpret_cast<unsigned*>(&l23));
            if (EPI == 1) {
                int ch = idx >> 5, mg = (idx & 31) * 4;
                auto Ath = reinterpret_cast<__nv_bfloat16(*)[LDT]>(smem_raw + buf * 8704);
                auto Atl = reinterpret_cast<__nv_bfloat16(*)[LDT]>(smem_raw + 20480 + buf * 8704);
                *reinterpret_cast<uint2*>(&Ath[ch][mg]) = hv;
                *reinterpret_cast<uint2*>(&Atl[ch][mg]) = lv;
            } else {
                int row = idx >> 3, c4 = (idx & 7) * 4;
                auto Ah = reinterpret_cast<__nv_bfloat16(*)[LDS]>(smem_raw + buf * 10240);
                auto Al = reinterpret_cast<__nv_bfloat16(*)[LDS]>(smem_raw + 20480 + buf * 10240);
                *reinterpret_cast<uint2*>(&Ah[row][c4]) = hv;
                *reinterpret_cast<uint2*>(&Al[row][c4]) = lv;
            }
        }
    };
    auto cpW = [&](int kt, int buf) {
        auto Bh = reinterpret_cast<__nv_bfloat16(*)[LDS]>(smem_raw + 40960 + buf * 10240);
        auto Bl = reinterpret_cast<__nv_bfloat16(*)[LDS]>(smem_raw + 61440 + buf * 10240);
#pragma unroll
        for (int u = 0; u < 2; ++u) {
            int idx = u * 256 + tid;
            int row = idx >> 2, c8 = (idx & 3) * 8;
            cpasync16(&Bh[row][c8], Whp + (size_t)(n0 + row) * kCh + kt + c8);
            cpasync16(&Bl[row][c8], Wlp + (size_t)(n0 + row) * kCh + kt + c8);
        }
    };

    float4 ra[4];
    ldgA(0, ra);
    cpW(0, 0);
    CP_COMMIT();

    for (int it = 0; it < 8; ++it) {
        const int cur = it & 1;
        stA(cur, ra);
        if (it < 7) ldgA((it + 1) * BK, ra);
        CP_WAIT0();
        __syncthreads();
        if (it < 7) { cpW((it + 1) * BK, cur ^ 1); CP_COMMIT(); }

        auto Ah  = reinterpret_cast<__nv_bfloat16(*)[LDS]>(smem_raw + cur * 10240);
        auto Al  = reinterpret_cast<__nv_bfloat16(*)[LDS]>(smem_raw + 20480 + cur * 10240);
        auto Ath = reinterpret_cast<__nv_bfloat16(*)[LDT]>(smem_raw + cur * 8704);
        auto Atl = reinterpret_cast<__nv_bfloat16(*)[LDT]>(smem_raw + 20480 + cur * 8704);
        auto Bh  = reinterpret_cast<__nv_bfloat16(*)[LDS]>(smem_raw + 40960 + cur * 10240);
        auto Bl  = reinterpret_cast<__nv_bfloat16(*)[LDS]>(smem_raw + 61440 + cur * 10240);
#pragma unroll
        for (int ks = 0; ks < 2; ++ks) {
            const int kb = ks * 16;
            unsigned ah[2][4], al[2][4];
#pragma unroll
            for (int mt = 0; mt < 2; ++mt) {
                if (EPI == 1) {
                    int krow = kb + ((lane >> 4) << 3) + (lane & 7);
                    int mcol = wr * 32 + mt * 16 + (((lane >> 3) & 1) << 3);
                    ldsm4t(ah[mt], &Ath[krow][mcol]);
                    ldsm4t(al[mt], &Atl[krow][mcol]);
                } else {
                    int arow = wr * 32 + mt * 16 + (lane & 15);
                    int koff = kb + ((lane >> 4) << 3);
                    ldsm4(ah[mt], &Ah[arow][koff]);
                    ldsm4(al[mt], &Al[arow][koff]);
                }
            }
#pragma unroll
            for (int g = 0; g < 4; ++g) {
                int nrow = wc * 64 + g * 16 + (lane & 7) + ((lane >> 4) << 3);
                int koff = kb + (((lane >> 3) & 1) << 3);
                unsigned bh[4], bl[4];
                ldsm4(bh, &Bh[nrow][koff]);
                ldsm4(bl, &Bl[nrow][koff]);
#pragma unroll
                for (int mt = 0; mt < 2; ++mt) {
                    mma16816(acc[mt][2 * g],     ah[mt], bh);
                    mma16816(acc[mt][2 * g],     ah[mt], bl);
                    mma16816(acc[mt][2 * g],     al[mt], bh);
                    mma16816(acc[mt][2 * g + 1], ah[mt], bh + 2);
                    mma16816(acc[mt][2 * g + 1], ah[mt], bl + 2);
                    mma16816(acc[mt][2 * g + 1], al[mt], bh + 2);
                }
            }
        }
    }
    __syncthreads();

    float* stage = reinterpret_cast<float*>(smem_raw);     // [128][129], EPI==0 only
#pragma unroll
    for (int mt = 0; mt < 2; ++mt) {
        int r0 = m0 + wr * 32 + mt * 16 + (lane >> 2);
        float sA = 0.f, sB = 0.f, qA = 0.f, qB = 0.f;      // EPI==1 LN partials
#pragma unroll
        for (int nt = 0; nt < 8; ++nt) {
            int col = n0 + wc * 64 + nt * 8 + (lane & 3) * 2;
            float* c = acc[mt][nt];
            float2 bv = *reinterpret_cast<const float2*>(bias + col);
            float v0 = c[0] + bv.x, v1 = c[1] + bv.y;
            float v2 = c[2] + bv.x, v3 = c[3] + bv.y;
            if (EPI == 1) {
                float2 s0 = *reinterpret_cast<const float2*>(g_xe + (size_t)r0 * kCh + col);
                float2 s1 = *reinterpret_cast<const float2*>(g_xe + (size_t)(r0 + 8) * kCh + col);
                v0 = gelu_exact(v0) + s0.x; v1 = gelu_exact(v1) + s0.y;
                v2 = gelu_exact(v2) + s1.x; v3 = gelu_exact(v3) + s1.y;
                sA += v0 + v1; qA += v0 * v0 + v1 * v1;
                sB += v2 + v3; qB += v2 * v2 + v3 * v3;
            } else {
                float me = fmaxf(fabsf(v0), fabsf(v2));
                float mo = fmaxf(fabsf(v1), fabsf(v3));
#pragma unroll
                for (int o = 4; o < 32; o <<= 1) {
                    me = fmaxf(me, __shfl_xor_sync(0xffffffffu, me, o));
                    mo = fmaxf(mo, __shfl_xor_sync(0xffffffffu, mo, o));
                }
                if (lane < 4) {
                    atomicMax(&red[col - n0],     __float_as_uint(me));
                    atomicMax(&red[col - n0 + 1], __float_as_uint(mo));
                }
            }
            if (EPI == 0) {
                int lr = r0 - m0, lc = col - n0;
                stage[lr * 129 + lc]           = v0;
                stage[lr * 129 + lc + 1]       = v1;
                stage[(lr + 8) * 129 + lc]     = v2;
                stage[(lr + 8) * 129 + lc + 1] = v3;
            }
            *reinterpret_cast<float2*>(Cp + (size_t)r0 * kCh + col)       = make_float2(v0, v1);
            *reinterpret_cast<float2*>(Cp + (size_t)(r0 + 8) * kCh + col) = make_float2(v2, v3);
        }
        if (EPI == 1) {
            // reduce over the 4 lanes sharing these rows (64 columns total)
#pragma unroll
            for (int o = 1; o <= 2; o <<= 1) {
                sA += __shfl_xor_sync(0xffffffffu, sA, o);
                qA += __shfl_xor_sync(0xffffffffu, qA, o);
                sB += __shfl_xor_sync(0xffffffffu, sB, o);
                qB += __shfl_xor_sync(0xffffffffu, qB, o);
            }
            if ((lane & 3) == 0) {
                int wcg = blockIdx.y * 2 + wc;
                g_psum [r0 * 4 + wcg]       = sA;
                g_psumq[r0 * 4 + wcg]       = qA;
                g_psum [(r0 + 8) * 4 + wcg] = sB;
                g_psumq[(r0 + 8) * 4 + wcg] = qB;
            }
        }
    }
    if (EPI != 1) {
        __syncthreads();
        if (tid < BN) {
            unsigned* buf = (EPI == 0) ? g_maxxe : g_maxy;
            atomicMax(&buf[bB * kCh + n0 + tid], red[tid]);
        }
    }
    if (EPI == 0) {
        __syncthreads();
        for (int i = tid; i < 128 * 128; i += 256) {
            int cidx = i >> 7, l = i & 127;
            g_xeT[((size_t)bB * kCh + n0 + cidx) * kSeq + l0m + l] = stage[l * 129 + cidx];
        }
    }
}

// ---------------------------------------------------------------------------
// Radix-8 Stockham FFT: 4 radix-8 stages + 1 radix-2 per direction.
template <bool INV>
__device__ __forceinline__ void dft4v(float2 a0, float2 a1, float2 a2, float2 a3,
                                      float2& y0, float2& y1, float2& y2, float2& y3) {
    float2 t0 = cadd(a0, a2), t1 = csub(a0, a2);
    float2 t2 = cadd(a1, a3), t3 = csub(a1, a3);
    y0 = cadd(t0, t2); y2 = csub(t0, t2);
    if (!INV) {
        y1 = make_float2(t1.x + t3.y, t1.y - t3.x);
        y3 = make_float2(t1.x - t3.y, t1.y + t3.x);
    } else {
        y1 = make_float2(t1.x - t3.y, t1.y + t3.x);
        y3 = make_float2(t1.x + t3.y, t1.y - t3.x);
    }
}

template <bool INV>
__device__ __forceinline__ void dft8v(const float2* a, float2* b) {
    const float C = 0.7071067811865476f;
    float2 E0, E1, E2, E3, O0, O1, O2, O3;
    dft4v<INV>(a[0], a[2], a[4], a[6], E0, E1, E2, E3);
    dft4v<INV>(a[1], a[3], a[5], a[7], O0, O1, O2, O3);
    float2 u1, u2, u3;
    if (!INV) {
        u1 = make_float2(C * (O1.x + O1.y), C * (O1.y - O1.x));
        u2 = make_float2(O2.y, -O2.x);
        u3 = make_float2(C * (O3.y - O3.x), -C * (O3.x + O3.y));
    } else {
        u1 = make_float2(C * (O1.x - O1.y), C * (O1.x + O1.y));
        u2 = make_float2(-O2.y, O2.x);
        u3 = make_float2(-C * (O3.x + O3.y), C * (O3.x - O3.y));
    }
    b[0] = cadd(E0, O0); b[4] = csub(E0, O0);
    b[1] = cadd(E1, u1); b[5] = csub(E1, u1);
    b[2] = cadd(E2, u2); b[6] = csub(E2, u2);
    b[3] = cadd(E3, u3); b[7] = csub(E3, u3);
}

template <bool INV>
__device__ __forceinline__ void fft_stages(float2*& src, float2*& dst, const float2* tw) {
    const int t = threadIdx.x;
    {
        float2 a[8], b[8];
#pragma unroll
        for (int j = 0; j < 8; ++j) a[j] = src[SWZ(t + j * 1024)];
        dft8v<INV>(a, b);
        float2 w1 = tw[t]; if (INV) w1.y = -w1.y;
        float2 w2 = cmul(w1, w1), w3 = cmul(w2, w1), w4 = cmul(w2, w2),
               w5 = cmul(w2, w3), w6 = cmul(w3, w3), w7 = cmul(w3, w4);
        float2 o1 = cmul(w1, b[1]), o2 = cmul(w2, b[2]), o3 = cmul(w3, b[3]),
               o4 = cmul(w4, b[4]), o5 = cmul(w5, b[5]), o6 = cmul(w6, b[6]),
               o7 = cmul(w7, b[7]);
        int base = 8 * t;
        *reinterpret_cast<float4*>(dst + SWZ(base))     = make_float4(b[0].x, b[0].y, o1.x, o1.y);
        *reinterpret_cast<float4*>(dst + SWZ(base + 2)) = make_float4(o2.x, o2.y, o3.x, o3.y);
        *reinterpret_cast<float4*>(dst + SWZ(base + 4)) = make_float4(o4.x, o4.y, o5.x, o5.y);
        *reinterpret_cast<float4*>(dst + SWZ(base + 6)) = make_float4(o6.x, o6.y, o7.x, o7.y);
        __syncthreads();
        float2* tp = src; src = dst; dst = tp;
    }
#pragma unroll
    for (int ls = 3; ls <= 9; ls += 3) {
        const int s = 1 << ls;
        int q = t & (s - 1), p = t >> ls;
        float2 a[8], b[8];
#pragma unroll
        for (int j = 0; j < 8; ++j) a[j] = src[SWZ(t + j * 1024)];
        dft8v<INV>(a, b);
        float2 w1 = tw[p << ls]; if (INV) w1.y = -w1.y;
        float2 w2 = cmul(w1, w1), w3 = cmul(w2, w1), w4 = cmul(w2, w2),
               w5 = cmul(w2, w3), w6 = cmul(w3, w3), w7 = cmul(w3, w4);
        int o = q + (p << (ls + 3));
        dst[SWZ(o)]         = b[0];
        dst[SWZ(o + s)]     = cmul(w1, b[1]);
        dst[SWZ(o + 2 * s)] = cmul(w2, b[2]);
        dst[SWZ(o + 3 * s)] = cmul(w3, b[3]);
        dst[SWZ(o + 4 * s)] = cmul(w4, b[4]);
        dst[SWZ(o + 5 * s)] = cmul(w5, b[5]);
        dst[SWZ(o + 6 * s)] = cmul(w6, b[6]);
        dst[SWZ(o + 7 * s)] = cmul(w7, b[7]);
        __syncthreads();
        float2* tp = src; src = dst; dst = tp;
    }
    for (int u = t; u < 4096; u += 1024) {
        float2 a = src[SWZ(u)], b = src[SWZ(u + 4096)];
        dst[SWZ(u)]        = cadd(a, b);
        dst[SWZ(u + 4096)] = csub(a, b);
    }
    __syncthreads();
    float2* tp = src; src = dst; dst = tp;
}

// One CTA per (b,c) row; writes y1T = gelu(h1T + h0*xeT) to g_y1.
__global__ __launch_bounds__(1024, 1) void fftconv_kernel(const float* __restrict__ h0p) {
    extern __shared__ float2 sm[];
    float2* tw8  = sm;
    float2* tw16 = sm + 4096;
    float2* b0   = sm + 8194;
    float2* b1   = b0 + kN2;
    for (int i = threadIdx.x; i < 4097; i += 1024) {
        if (i < 4096) tw8[i] = g_tw8[i];
        tw16[i] = g_tw16[i];
    }
    const int r = blockIdx.x, c = r & (kCh - 1);
    const float2* row2 = reinterpret_cast<const float2*>(g_xeT + (size_t)r * kSeq);
    for (int n = threadIdx.x; n < kN2; n += 1024)
        b0[SWZ(n)] = (n < 4096) ? row2[n] : make_float2(0.f, 0.f);
    __syncthreads();

    float2 *src = b0, *dst = b1;
    fft_stages<false>(src, dst, tw8);

    const float2* Kfc = g_Kf + (size_t)c * kNF;
    for (int k = threadIdx.x; k <= 4096; k += 1024) {
        int j = (kN2 - k) & (kN2 - 1);
        float2 Zk = src[SWZ(k)], Zj = src[SWZ(j)];
        float2 E = make_float2(0.5f * (Zk.x + Zj.x), 0.5f * (Zk.y - Zj.y));
        float2 O = make_float2(0.5f * (Zk.y + Zj.y), -0.5f * (Zk.x - Zj.x));
        float2 w = tw16[k];
        float2 wO = cmul(w, O);
        float2 Xk = make_float2(E.x + wO.x, E.y + wO.y);
        float2 Xj = make_float2(E.x - wO.x, -(E.y - wO.y));
        float2 Yk = cmul(Xk, Kfc[k]);
        float2 Yj = cmul(Xj, Kfc[kN2 - k]);
        float2 Ey = make_float2(0.5f * (Yk.x + Yj.x), 0.5f * (Yk.y - Yj.y));
        float2 Dy = make_float2(0.5f * (Yk.x - Yj.x), 0.5f * (Yk.y + Yj.y));
        float2 Oy = cmul(make_float2(w.x, -w.y), Dy);
        dst[SWZ(k)] = make_float2(Ey.x - Oy.y, Ey.y + Oy.x);
        if (k >= 1 && k < 4096) {
            float2 Em = make_float2(0.5f * (Yj.x + Yk.x), 0.5f * (Yj.y - Yk.y));
            float2 Dm = make_float2(0.5f * (Yj.x - Yk.x), 0.5f * (Yj.y + Yk.y));
            float2 Om = cmul(make_float2(-w.x, -w.y), Dm);
            dst[SWZ(kN2 - k)] = make_float2(Em.x - Om.y, Em.y + Om.x);
        }
    }
    __syncthreads();
    { float2* tp = src; src = dst; dst = tp; }

    fft_stages<true>(src, dst, tw8);

    const float h0v = h0p[0];
    float2* y1row = reinterpret_cast<float2*>(g_y1 + (size_t)r * kSeq);
    for (int n = threadIdx.x; n < 4096; n += 1024) {
        float2 v = src[SWZ(n)];
        float2 e = row2[n];
        y1row[n] = make_float2(gelu_exact(v.x + h0v * e.x),
                               gelu_exact(v.y + h0v * e.y));
    }
}

__global__ void hout_kernel(float* __restrict__ h) {
    int i = blockIdx.x * 256 + threadIdx.x;
    if (i < kB * kCh)
        h[i] = __uint_as_float(g_maxy[i]) / (__uint_as_float(g_maxxe[i]) + 1e-6f);
}

extern "C" void kernel_launch(void* const* d_in, const int* in_sizes, int n_in,
                              void* d_out, int out_size) {
    const float* x     = (const float*)d_in[0];
    const float* A     = (const float*)d_in[1];
    const float* Bp    = (const float*)d_in[2];
    const float* h0    = (const float*)d_in[3];
    const float* W_enc = (const float*)d_in[4];
    const float* b_enc = (const float*)d_in[5];
    const float* W_fc  = (const float*)d_in[6];
    const float* b_fc  = (const float*)d_in[7];
    const float* gamma = (const float*)d_in[8];
    const float* beta  = (const float*)d_in[9];
    const float* W_dec = (const float*)d_in[10];
    const float* b_dec = (const float*)d_in[11];
    float* out = (float*)d_out;

    static cudaStream_t side = nullptr;
    static cudaEvent_t evFork = nullptr, evJoin = nullptr;
    static bool attrsSet = false;
    if (!side) {
        cudaStreamCreateWithFlags(&side, cudaStreamNonBlocking);
        cudaEventCreateWithFlags(&evFork, cudaEventDisableTiming);
        cudaEventCreateWithFlags(&evJoin, cudaEventDisableTiming);
    }
    const int kSmemFFT = 24578 * 8;   // 196624 B dynamic SMEM
    if (!attrsSet) {
        cudaFuncSetAttribute(fftconv_kernel, cudaFuncAttributeMaxDynamicSharedMemorySize, kSmemFFT);
        cudaFuncSetAttribute(gemm_kernel<0>, cudaFuncAttributeMaxDynamicSharedMemorySize, kGemmSmem);
        cudaFuncSetAttribute(gemm_kernel<1>, cudaFuncAttributeMaxDynamicSharedMemorySize, kGemmSmem);
        cudaFuncSetAttribute(gemm_kernel<2>, cudaFuncAttributeMaxDynamicSharedMemorySize, kGemmSmem);
        attrsSet = true;
    }

    cudaEventRecord(evFork, 0);
    cudaStreamWaitEvent(side, evFork, 0);
    twiddle_kernel<<<17, 256, 0, side>>>();
    kfgen_kernel<<<dim3(33, kCh), 256, 0, side>>>(A, Bp);
    cudaEventRecord(evJoin, side);

    zero_kernel<<<8, 256>>>();
    wsplit_kernel<<<dim3(kCh * kCh / 256, 3), 256>>>(W_enc, W_fc, W_dec);
    gemm_kernel<0><<<dim3(kM / 128, 2), 256, kGemmSmem>>>(x, b_enc, nullptr, nullptr, nullptr);
    cudaStreamWaitEvent(0, evJoin, 0);
    fftconv_kernel<<<kB * kCh, 1024, kSmemFFT>>>(h0);
    gemm_kernel<1><<<dim3(kM / 128, 2), 256, kGemmSmem>>>(nullptr, b_fc, nullptr, nullptr, nullptr);
    lnstats_kernel<<<kM / 256, 256>>>();
    gemm_kernel<2><<<dim3(kM / 128, 2), 256, kGemmSmem>>>(nullptr, b_dec, out, gamma, beta);
    hout_kernel<<<8, 256>>>(out + (size_t)kM * kCh);
}

// round 17
// speedup vs baseline: 1.0759x; 1.0759x over previous
#include <cuda_runtime.h>
#include <cuda_bf16.h>

constexpr int kB = 8, kSeq = 8192, kCh = 256;
constexpr int kM  = kB * kSeq;          // 65536
constexpr int kN2 = 8192;               // complex FFT size (real 16384)
constexpr int kNF = 8193;               // rfft bins of 16384

__device__ __align__(128) float  g_xe [kM * kCh];   // (B,L,C)
__device__ __align__(128) float  g_xeT[kM * kCh];   // (B,C,L), preserved
__device__ __align__(128) float  g_y1 [kM * kCh];   // (B,C,L)  y1T
__device__ __align__(128) float  g_y2 [kM * kCh];   // (B,L,C), un-normalized
__device__ __align__(128) float2 g_Kf [(size_t)kCh * kNF];
__device__ __align__(128) __nv_bfloat16 g_Wh[3 * kCh * kCh];
__device__ __align__(128) __nv_bfloat16 g_Wl[3 * kCh * kCh];
__device__ float2 g_tw8 [4096];
__device__ float2 g_tw16[4097];
__device__ float  g_psum [kM * 4];
__device__ float  g_psumq[kM * 4];
__device__ float  g_mu[kM], g_rstd[kM];
__device__ unsigned g_maxxe[kB * kCh];
__device__ unsigned g_maxy [kB * kCh];

#define SWZ(i) ((i) ^ ((((i) >> 4) & 3) << 2))

__device__ __forceinline__ float2 cmul(float2 a, float2 b) {
    return make_float2(a.x * b.x - a.y * b.y, a.x * b.y + a.y * b.x);
}
__device__ __forceinline__ float2 cadd(float2 a, float2 b) {
    return make_float2(a.x + b.x, a.y + b.y);
}
__device__ __forceinline__ float2 csub(float2 a, float2 b) {
    return make_float2(a.x - b.x, a.y - b.y);
}
__device__ __forceinline__ float gelu_exact(float v) {
    return 0.5f * v * (1.0f + erff(v * 0.7071067811865476f));
}
__device__ __forceinline__ void ldsm4(unsigned* r, const void* p) {
    unsigned addr = (unsigned)__cvta_generic_to_shared(p);
    asm volatile("ldmatrix.sync.aligned.m8n8.x4.shared.b16 {%0,%1,%2,%3}, [%4];"
                 : "=r"(r[0]), "=r"(r[1]), "=r"(r[2]), "=r"(r[3]) : "r"(addr));
}
__device__ __forceinline__ void ldsm4t(unsigned* r, const void* p) {
    unsigned addr = (unsigned)__cvta_generic_to_shared(p);
    asm volatile("ldmatrix.sync.aligned.m8n8.x4.trans.shared.b16 {%0,%1,%2,%3}, [%4];"
                 : "=r"(r[0]), "=r"(r[1]), "=r"(r[2]), "=r"(r[3]) : "r"(addr));
}
__device__ __forceinline__ void mma16816(float* d, const unsigned* a, const unsigned* b) {
    asm volatile("mma.sync.aligned.m16n8k16.row.col.f32.bf16.bf16.f32 "
                 "{%0,%1,%2,%3}, {%4,%5,%6,%7}, {%8,%9}, {%0,%1,%2,%3};"
                 : "+f"(d[0]), "+f"(d[1]), "+f"(d[2]), "+f"(d[3])
                 : "r"(a[0]), "r"(a[1]), "r"(a[2]), "r"(a[3]), "r"(b[0]), "r"(b[1]));
}
__device__ __forceinline__ void cpasync16(void* smem_dst, const void* gsrc) {
    unsigned a = (unsigned)__cvta_generic_to_shared(smem_dst);
    asm volatile("cp.async.cg.shared.global [%0], [%1], 16;" :: "r"(a), "l"(gsrc));
}
#define CP_COMMIT() asm volatile("cp.async.commit_group;")
#define CP_WAIT0()  asm volatile("cp.async.wait_group 0;")

__global__ void zero_kernel() {
    int i = blockIdx.x * 256 + threadIdx.x;
    if (i < kB * kCh) { g_maxxe[i] = 0u; g_maxy[i] = 0u; }
}

__global__ void twiddle_kernel() {
    int i = blockIdx.x * 256 + threadIdx.x;
    float s, c;
    if (i < 4096) { sincospif(-2.0f * i / 8192.0f,  &s, &c); g_tw8 [i] = make_float2(c, s); }
    if (i < 4097) { sincospif(-2.0f * i / 16384.0f, &s, &c); g_tw16[i] = make_float2(c, s); }
}

__global__ void wsplit_kernel(const float* __restrict__ We, const float* __restrict__ Wf,
                              const float* __restrict__ Wd) {
    int i = blockIdx.x * 256 + threadIdx.x;
    const float* src = (blockIdx.y == 0) ? We : (blockIdx.y == 1 ? Wf : Wd);
    float v = src[i];
    __nv_bfloat16 h = __float2bfloat16(v);
    g_Wh[blockIdx.y * kCh * kCh + i] = h;
    g_Wl[blockIdx.y * kCh * kCh + i] = __float2bfloat16(v - __bfloat162float(h));
}

// Kf[c][k] = B(w)/A(w)/8192 (IIR tail underflows fp32 beyond n=8192).
__global__ __launch_bounds__(256) void kfgen_kernel(const float* __restrict__ A,
                                                    const float* __restrict__ Bp) {
    __shared__ float sA[64], sB[64];
    int c = blockIdx.y;
    if (threadIdx.x < 64)       sA[threadIdx.x]      = A [c * 64 + threadIdx.x];
    else if (threadIdx.x < 128) sB[threadIdx.x - 64] = Bp[c * 64 + threadIdx.x - 64];
    __syncthreads();
    int k = blockIdx.x * 256 + threadIdx.x;
    if (k >= kNF) return;
    float sv, cv;
    sincospif(-(float)k / 8192.0f, &sv, &cv);
    float2 w  = make_float2(cv, sv);
    float2 w2 = cmul(w, w);
    float2 ae = make_float2(sA[63], 0.f);
    float2 ao = make_float2(sA[62], 0.f);
    float2 be = make_float2(sB[62], 0.f);
    float2 bo = make_float2(sB[63], 0.f);
#pragma unroll 4
    for (int i = 31; i >= 1; --i) {
        ae = cmul(ae, w2); ae.x += sA[2 * i - 1];
        ao = cmul(ao, w2); ao.x += sA[2 * i - 2];
        be = cmul(be, w2); be.x += sB[2 * i - 2];
        bo = cmul(bo, w2); bo.x += sB[2 * i - 1];
    }
    ae = cmul(ae, w2); ae.x += 1.0f;
    float2 av = cadd(ae, cmul(w, ao));
    float2 bv = cadd(be, cmul(w, bo));
    float scl = (1.0f / 8192.0f) / (av.x * av.x + av.y * av.y);
    g_Kf[(size_t)c * kNF + k] = make_float2((bv.x * av.x + bv.y * av.y) * scl,
                                            (bv.y * av.x - bv.x * av.y) * scl);
}

// Fold the 4 per-row LN partials (fixed order -> deterministic).
__global__ void lnstats_kernel() {
    int r = blockIdx.x * 256 + threadIdx.x;
    float4 p = *reinterpret_cast<const float4*>(g_psum  + 4 * r);
    float4 q = *reinterpret_cast<const float4*>(g_psumq + 4 * r);
    float s  = (p.x + p.y) + (p.z + p.w);
    float qq = (q.x + q.y) + (q.z + q.w);
    float mu = s * (1.f / 256.f);
    g_mu[r]   = mu;
    g_rstd[r] = rsqrtf(qq * (1.f / 256.f) - mu * mu + 1e-5f);
}

// ---------------------------------------------------------------------------
// Tensor-core GEMM (3-pass bf16 split), software-pipelined.
// EPI 0: encode (x -> g_xe + g_xeT, colmax)
// EPI 1: fc     (A from y1T via ldmatrix.trans; out gelu+skip -> g_y2; LN partials)
// EPI 2: decode (A = LN(g_y2) applied on the fly; out -> d_out, colmax)
constexpr int kGemmSmem = 81920 + 512;

template <int EPI>
__global__ __launch_bounds__(256, 2) void gemm_kernel(const float* __restrict__ Ain,
                                                      const float* __restrict__ bias,
                                                      float* __restrict__ Cout,
                                                      const float* __restrict__ lng,
                                                      const float* __restrict__ lnb) {
    constexpr int BM = 128, BN = 128, BK = 32, LDS = 40, LDT = 136;
    extern __shared__ __align__(16) unsigned char smem_raw[];
    unsigned* red = reinterpret_cast<unsigned*>(smem_raw + 81920);
    const float* Ap = (EPI == 1) ? g_y1 : (EPI == 2 ? g_y2 : Ain);
    float*       Cp = (EPI == 0) ? g_xe : (EPI == 1 ? g_y2 : Cout);
    const __nv_bfloat16* Whp = g_Wh + EPI * kCh * kCh;
    const __nv_bfloat16* Wlp = g_Wl + EPI * kCh * kCh;
    const int m0 = blockIdx.x * BM, n0 = blockIdx.y * BN;
    const int tid = threadIdx.x, lane = tid & 31, warp = tid >> 5;
    const int wr = warp >> 1, wc = warp & 1;
    const int bB = m0 >> 13, l0m = m0 & (kSeq - 1);

    if (EPI != 1 && tid < BN) red[tid] = 0u;

    float acc[2][8][4];
#pragma unroll
    for (int mt = 0; mt < 2; ++mt)
#pragma unroll
        for (int nt = 0; nt < 8; ++nt)
#pragma unroll
            for (int r = 0; r < 4; ++r) acc[mt][nt][r] = 0.f;

    auto ldgA = [&](int kt, float4* ra) {
#pragma unroll
        for (int u = 0; u < 4; ++u) {
            int idx = u * 256 + tid;
            if (EPI == 1) {
                int ch = idx >> 5, mg = (idx & 31) * 4;
                ra[u] = *reinterpret_cast<const float4*>(
                    Ap + ((size_t)bB * kCh + kt + ch) * kSeq + l0m + mg);
            } else {
                int row = idx >> 3, c4 = (idx & 7) * 4;
                float4 v = *reinterpret_cast<const float4*>(
                    Ap + (size_t)(m0 + row) * kCh + kt + c4);
                if (EPI == 2) {
                    float mu = g_mu[m0 + row], rs = g_rstd[m0 + row];
                    float4 gv = *reinterpret_cast<const float4*>(lng + kt + c4);
                    float4 bv = *reinterpret_cast<const float4*>(lnb + kt + c4);
                    v.x = (v.x - mu) * rs * gv.x + bv.x;
                    v.y = (v.y - mu) * rs * gv.y + bv.y;
                    v.z = (v.z - mu) * rs * gv.z + bv.z;
                    v.w = (v.w - mu) * rs * gv.w + bv.w;
                }
                ra[u] = v;
            }
        }
    };
    auto stA = [&](int buf, const float4* ra) {
#pragma unroll
        for (int u = 0; u < 4; ++u) {
            int idx = u * 256 + tid;
            float4 v = ra[u];
            __nv_bfloat162 h01 = __floats2bfloat162_rn(v.x, v.y);
            __nv_bfloat162 h23 = __floats2bfloat162_rn(v.z, v.w);
            __nv_bfloat162 l01 = __floats2bfloat162_rn(v.x - __low2float(h01),
                                                       v.y - __high2float(h01));
            __nv_bfloat162 l23 = __floats2bfloat162_rn(v.z - __low2float(h23),
                                                       v.w - __high2float(h23));
            uint2 hv = make_uint2(*reinterpret_cast<unsigned*>(&h01),
                                  *reinterpret_cast<unsigned*>(&h23));
            uint2 lv = make_uint2(*reinterpret_cast<unsigned*>(&l01),
                                  *reinterpret_cast<unsigned*>(&l23));
            if (EPI == 1) {
                int ch = idx >> 5, mg = (idx & 31) * 4;
                auto Ath = reinterpret_cast<__nv_bfloat16(*)[LDT]>(smem_raw + buf * 8704);
                auto Atl = reinterpret_cast<__nv_bfloat16(*)[LDT]>(smem_raw + 20480 + buf * 8704);
                *reinterpret_cast<uint2*>(&Ath[ch][mg]) = hv;
                *reinterpret_cast<uint2*>(&Atl[ch][mg]) = lv;
            } else {
                int row = idx >> 3, c4 = (idx & 7) * 4;
                auto Ah = reinterpret_cast<__nv_bfloat16(*)[LDS]>(smem_raw + buf * 10240);
                auto Al = reinterpret_cast<__nv_bfloat16(*)[LDS]>(smem_raw + 20480 + buf * 10240);
                *reinterpret_cast<uint2*>(&Ah[row][c4]) = hv;
                *reinterpret_cast<uint2*>(&Al[row][c4]) = lv;
            }
        }
    };
    auto cpW = [&](int kt, int buf) {
        auto Bh = reinterpret_cast<__nv_bfloat16(*)[LDS]>(smem_raw + 40960 + buf * 10240);
        auto Bl = reinterpret_cast<__nv_bfloat16(*)[LDS]>(smem_raw + 61440 + buf * 10240);
#pragma unroll
        for (int u = 0; u < 2; ++u) {
            int idx = u * 256 + tid;
            int row = idx >> 2, c8 = (idx & 3) * 8;
            cpasync16(&Bh[row][c8], Whp + (size_t)(n0 + row) * kCh + kt + c8);
            cpasync16(&Bl[row][c8], Wlp + (size_t)(n0 + row) * kCh + kt + c8);
        }
    };

    float4 ra[4];
    ldgA(0, ra);
    cpW(0, 0);
    CP_COMMIT();

    for (int it = 0; it < 8; ++it) {
        const int cur = it & 1;
        stA(cur, ra);
        if (it < 7) ldgA((it + 1) * BK, ra);
        CP_WAIT0();
        __syncthreads();
        if (it < 7) { cpW((it + 1) * BK, cur ^ 1); CP_COMMIT(); }

        auto Ah  = reinterpret_cast<__nv_bfloat16(*)[LDS]>(smem_raw + cur * 10240);
        auto Al  = reinterpret_cast<__nv_bfloat16(*)[LDS]>(smem_raw + 20480 + cur * 10240);
        auto Ath = reinterpret_cast<__nv_bfloat16(*)[LDT]>(smem_raw + cur * 8704);
        auto Atl = reinterpret_cast<__nv_bfloat16(*)[LDT]>(smem_raw + 20480 + cur * 8704);
        auto Bh  = reinterpret_cast<__nv_bfloat16(*)[LDS]>(smem_raw + 40960 + cur * 10240);
        auto Bl  = reinterpret_cast<__nv_bfloat16(*)[LDS]>(smem_raw + 61440 + cur * 10240);
#pragma unroll
        for (int ks = 0; ks < 2; ++ks) {
            const int kb = ks * 16;
            unsigned ah[2][4], al[2][4];
#pragma unroll
            for (int mt = 0; mt < 2; ++mt) {
                if (EPI == 1) {
                    int krow = kb + ((lane >> 4) << 3) + (lane & 7);
                    int mcol = wr * 32 + mt * 16 + (((lane >> 3) & 1) << 3);
                    ldsm4t(ah[mt], &Ath[krow][mcol]);
                    ldsm4t(al[mt], &Atl[krow][mcol]);
                } else {
                    int arow = wr * 32 + mt * 16 + (lane & 15);
                    int koff = kb + ((lane >> 4) << 3);
                    ldsm4(ah[mt], &Ah[arow][koff]);
                    ldsm4(al[mt], &Al[arow][koff]);
                }
            }
#pragma unroll
            for (int g = 0; g < 4; ++g) {
                int nrow = wc * 64 + g * 16 + (lane & 7) + ((lane >> 4) << 3);
                int koff = kb + (((lane >> 3) & 1) << 3);
                unsigned bh[4], bl[4];
                ldsm4(bh, &Bh[nrow][koff]);
                ldsm4(bl, &Bl[nrow][koff]);
#pragma unroll
                for (int mt = 0; mt < 2; ++mt) {
                    mma16816(acc[mt][2 * g],     ah[mt], bh);
                    mma16816(acc[mt][2 * g],     ah[mt], bl);
                    mma16816(acc[mt][2 * g],     al[mt], bh);
                    mma16816(acc[mt][2 * g + 1], ah[mt], bh + 2);
                    mma16816(acc[mt][2 * g + 1], ah[mt], bl + 2);
                    mma16816(acc[mt][2 * g + 1], al[mt], bh + 2);
                }
            }
        }
    }
    __syncthreads();

    float* stage = reinterpret_cast<float*>(smem_raw);     // [128][129], EPI==0 only
#pragma unroll
    for (int mt = 0; mt < 2; ++mt) {
        int r0 = m0 + wr * 32 + mt * 16 + (lane >> 2);
        float sA = 0.f, sB = 0.f, qA = 0.f, qB = 0.f;      // EPI==1 LN partials
#pragma unroll
        for (int nt = 0; nt < 8; ++nt) {
            int col = n0 + wc * 64 + nt * 8 + (lane & 3) * 2;
            float* c = acc[mt][nt];
            float2 bv = *reinterpret_cast<const float2*>(bias + col);
            float v0 = c[0] + bv.x, v1 = c[1] + bv.y;
            float v2 = c[2] + bv.x, v3 = c[3] + bv.y;
            if (EPI == 1) {
                float2 s0 = *reinterpret_cast<const float2*>(g_xe + (size_t)r0 * kCh + col);
                float2 s1 = *reinterpret_cast<const float2*>(g_xe + (size_t)(r0 + 8) * kCh + col);
                v0 = gelu_exact(v0) + s0.x; v1 = gelu_exact(v1) + s0.y;
                v2 = gelu_exact(v2) + s1.x; v3 = gelu_exact(v3) + s1.y;
                sA += v0 + v1; qA += v0 * v0 + v1 * v1;
                sB += v2 + v3; qB += v2 * v2 + v3 * v3;
            } else {
                float me = fmaxf(fabsf(v0), fabsf(v2));
                float mo = fmaxf(fabsf(v1), fabsf(v3));
#pragma unroll
                for (int o = 4; o < 32; o <<= 1) {
                    me = fmaxf(me, __shfl_xor_sync(0xffffffffu, me, o));
                    mo = fmaxf(mo, __shfl_xor_sync(0xffffffffu, mo, o));
                }
                if (lane < 4) {
                    atomicMax(&red[col - n0],     __float_as_uint(me));
                    atomicMax(&red[col - n0 + 1], __float_as_uint(mo));
                }
            }
            if (EPI == 0) {
                int lr = r0 - m0, lc = col - n0;
                stage[lr * 129 + lc]           = v0;
                stage[lr * 129 + lc + 1]       = v1;
                stage[(lr + 8) * 129 + lc]     = v2;
                stage[(lr + 8) * 129 + lc + 1] = v3;
            }
            *reinterpret_cast<float2*>(Cp + (size_t)r0 * kCh + col)       = make_float2(v0, v1);
            *reinterpret_cast<float2*>(Cp + (size_t)(r0 + 8) * kCh + col) = make_float2(v2, v3);
        }
        if (EPI == 1) {
#pragma unroll
            for (int o = 1; o <= 2; o <<= 1) {
                sA += __shfl_xor_sync(0xffffffffu, sA, o);
                qA += __shfl_xor_sync(0xffffffffu, qA, o);
                sB += __shfl_xor_sync(0xffffffffu, sB, o);
                qB += __shfl_xor_sync(0xffffffffu, qB, o);
            }
            if ((lane & 3) == 0) {
                int wcg = blockIdx.y * 2 + wc;
                g_psum [r0 * 4 + wcg]       = sA;
                g_psumq[r0 * 4 + wcg]       = qA;
                g_psum [(r0 + 8) * 4 + wcg] = sB;
                g_psumq[(r0 + 8) * 4 + wcg] = qB;
            }
        }
    }
    if (EPI != 1) {
        __syncthreads();
        if (tid < BN) {
            unsigned* buf = (EPI == 0) ? g_maxxe : g_maxy;
            atomicMax(&buf[bB * kCh + n0 + tid], red[tid]);
        }
    }
    if (EPI == 0) {
        __syncthreads();
        for (int i = tid; i < 128 * 128; i += 256) {
            int cidx = i >> 7, l = i & 127;
            g_xeT[((size_t)bB * kCh + n0 + cidx) * kSeq + l0m + l] = stage[l * 129 + cidx];
        }
    }
}

// ---------------------------------------------------------------------------
// Radix-8 Stockham FFT, fused ends:
//   fwd: stage1 reads gmem (zero-pad folded), 3 radix-8 stages; final radix-2
//        folded into the spectral pass. inv: stage1 + 3 radix-8 stages; final
//        radix-2 folded into the output. All values bit-identical to unfused.
template <bool INV>
__device__ __forceinline__ void dft4v(float2 a0, float2 a1, float2 a2, float2 a3,
                                      float2& y0, float2& y1, float2& y2, float2& y3) {
    float2 t0 = cadd(a0, a2), t1 = csub(a0, a2);
    float2 t2 = cadd(a1, a3), t3 = csub(a1, a3);
    y0 = cadd(t0, t2); y2 = csub(t0, t2);
    if (!INV) {
        y1 = make_float2(t1.x + t3.y, t1.y - t3.x);
        y3 = make_float2(t1.x - t3.y, t1.y + t3.x);
    } else {
        y1 = make_float2(t1.x - t3.y, t1.y + t3.x);
        y3 = make_float2(t1.x + t3.y, t1.y - t3.x);
    }
}

template <bool INV>
__device__ __forceinline__ void dft8v(const float2* a, float2* b) {
    const float C = 0.7071067811865476f;
    float2 E0, E1, E2, E3, O0, O1, O2, O3;
    dft4v<INV>(a[0], a[2], a[4], a[6], E0, E1, E2, E3);
    dft4v<INV>(a[1], a[3], a[5], a[7], O0, O1, O2, O3);
    float2 u1, u2, u3;
    if (!INV) {
        u1 = make_float2(C * (O1.x + O1.y), C * (O1.y - O1.x));
        u2 = make_float2(O2.y, -O2.x);
        u3 = make_float2(C * (O3.y - O3.x), -C * (O3.x + O3.y));
    } else {
        u1 = make_float2(C * (O1.x - O1.y), C * (O1.x + O1.y));
        u2 = make_float2(-O2.y, O2.x);
        u3 = make_float2(-C * (O3.x + O3.y), C * (O3.x - O3.y));
    }
    b[0] = cadd(E0, O0); b[4] = csub(E0, O0);
    b[1] = cadd(E1, u1); b[5] = csub(E1, u1);
    b[2] = cadd(E2, u2); b[6] = csub(E2, u2);
    b[3] = cadd(E3, u3); b[7] = csub(E3, u3);
}

// Twiddled write of one radix-8 butterfly at s=1 (consecutive, float4).
template <bool INV>
__device__ __forceinline__ void stage1_store(float2* dst, const float2* tw, int t,
                                             const float2* b) {
    float2 w1 = tw[t]; if (INV) w1.y = -w1.y;
    float2 w2 = cmul(w1, w1), w3 = cmul(w2, w1), w4 = cmul(w2, w2),
           w5 = cmul(w2, w3), w6 = cmul(w3, w3), w7 = cmul(w3, w4);
    float2 o1 = cmul(w1, b[1]), o2 = cmul(w2, b[2]), o3 = cmul(w3, b[3]),
           o4 = cmul(w4, b[4]), o5 = cmul(w5, b[5]), o6 = cmul(w6, b[6]),
           o7 = cmul(w7, b[7]);
    int base = 8 * t;
    *reinterpret_cast<float4*>(dst + SWZ(base))     = make_float4(b[0].x, b[0].y, o1.x, o1.y);
    *reinterpret_cast<float4*>(dst + SWZ(base + 2)) = make_float4(o2.x, o2.y, o3.x, o3.y);
    *reinterpret_cast<float4*>(dst + SWZ(base + 4)) = make_float4(o4.x, o4.y, o5.x, o5.y);
    *reinterpret_cast<float4*>(dst + SWZ(base + 6)) = make_float4(o6.x, o6.y, o7.x, o7.y);
}

// One middle radix-8 stage (ls = 3, 6, 9).
template <bool INV>
__device__ __forceinline__ void radix8_mid(const float2* src, float2* dst,
                                           const float2* tw, int ls) {
    const int t = threadIdx.x;
    const int s = 1 << ls;
    int q = t & (s - 1), p = t >> ls;
    float2 a[8], b[8];
#pragma unroll
    for (int j = 0; j < 8; ++j) a[j] = src[SWZ(t + j * 1024)];
    dft8v<INV>(a, b);
    float2 w1 = tw[p << ls]; if (INV) w1.y = -w1.y;
    float2 w2 = cmul(w1, w1), w3 = cmul(w2, w1), w4 = cmul(w2, w2),
           w5 = cmul(w2, w3), w6 = cmul(w3, w3), w7 = cmul(w3, w4);
    int o = q + (p << (ls + 3));
    dst[SWZ(o)]         = b[0];
    dst[SWZ(o + s)]     = cmul(w1, b[1]);
    dst[SWZ(o + 2 * s)] = cmul(w2, b[2]);
    dst[SWZ(o + 3 * s)] = cmul(w3, b[3]);
    dst[SWZ(o + 4 * s)] = cmul(w4, b[4]);
    dst[SWZ(o + 5 * s)] = cmul(w5, b[5]);
    dst[SWZ(o + 6 * s)] = cmul(w6, b[6]);
    dst[SWZ(o + 7 * s)] = cmul(w7, b[7]);
}

// One CTA per (b,c) row; writes y1T = gelu(h1T + h0*xeT) to g_y1.
__global__ __launch_bounds__(1024, 1) void fftconv_kernel(const float* __restrict__ h0p) {
    extern __shared__ float2 sm[];
    float2* tw8  = sm;
    float2* tw16 = sm + 4096;
    float2* b0   = sm + 8194;
    float2* b1   = b0 + kN2;
    for (int i = threadIdx.x; i < 4097; i += 1024) {
        if (i < 4096) tw8[i] = g_tw8[i];
        tw16[i] = g_tw16[i];
    }
    const int r = blockIdx.x, c = r & (kCh - 1);
    const float2* row2 = reinterpret_cast<const float2*>(g_xeT + (size_t)r * kSeq);
    const int t = threadIdx.x;
    __syncthreads();            // tw tables ready

    // Forward stage 1: read input directly from gmem; upper half is zero-pad.
    {
        float2 a[8], b[8];
#pragma unroll
        for (int j = 0; j < 4; ++j) a[j] = row2[t + j * 1024];
#pragma unroll
        for (int j = 4; j < 8; ++j) a[j] = make_float2(0.f, 0.f);
        dft8v<false>(a, b);
        stage1_store<false>(b0, tw8, t, b);
    }
    __syncthreads();
    float2 *src = b0, *dst = b1;
#pragma unroll
    for (int ls = 3; ls <= 9; ls += 3) {
        radix8_mid<false>(src, dst, tw8, ls);
        __syncthreads();
        float2* tp = src; src = dst; dst = tp;
    }
    // src holds S (pre-final-radix-2); the radix-2 is fused into the spectral op:
    // Z[k] = S[k]+S[k+4096] (k<4096), Z[k+4096] = S[k]-S[k+4096].
    const float2* Kfc = g_Kf + (size_t)c * kNF;
    for (int k = t; k <= 4096; k += 1024) {
        int u  = k & 4095;
        float2 Su  = src[SWZ(u)],  Su2 = src[SWZ(u + 4096)];
        float2 Zk = (k == 4096) ? csub(Su, Su2) : cadd(Su, Su2);
        int uj = (4096 - k) & 4095;
        float2 Tj  = src[SWZ(uj)], Tj2 = src[SWZ(uj + 4096)];
        float2 Zj = (k == 0) ? cadd(Tj, Tj2) : csub(Tj, Tj2);
        float2 E = make_float2(0.5f * (Zk.x + Zj.x), 0.5f * (Zk.y - Zj.y));
        float2 O = make_float2(0.5f * (Zk.y + Zj.y), -0.5f * (Zk.x - Zj.x));
        float2 w = tw16[k];
        float2 wO = cmul(w, O);
        float2 Xk = make_float2(E.x + wO.x, E.y + wO.y);
        float2 Xj = make_float2(E.x - wO.x, -(E.y - wO.y));
        float2 Yk = cmul(Xk, Kfc[k]);
        float2 Yj = cmul(Xj, Kfc[kN2 - k]);
        float2 Ey = make_float2(0.5f * (Yk.x + Yj.x), 0.5f * (Yk.y - Yj.y));
        float2 Dy = make_float2(0.5f * (Yk.x - Yj.x), 0.5f * (Yk.y + Yj.y));
        float2 Oy = cmul(make_float2(w.x, -w.y), Dy);
        dst[SWZ(k)] = make_float2(Ey.x - Oy.y, Ey.y + Oy.x);
        if (k >= 1 && k < 4096) {
            float2 Em = make_float2(0.5f * (Yj.x + Yk.x), 0.5f * (Yj.y - Yk.y));
            float2 Dm = make_float2(0.5f * (Yj.x - Yk.x), 0.5f * (Yj.y + Yk.y));
            float2 Om = cmul(make_float2(-w.x, -w.y), Dm);
            dst[SWZ(kN2 - k)] = make_float2(Em.x - Om.y, Em.y + Om.x);
        }
    }
    __syncthreads();
    { float2* tp = src; src = dst; dst = tp; }

    // Inverse: stage 1 + three mid stages; final radix-2 fused into the output.
    {
        float2 a[8], b[8];
#pragma unroll
        for (int j = 0; j < 8; ++j) a[j] = src[SWZ(t + j * 1024)];
        dft8v<true>(a, b);
        stage1_store<true>(dst, tw8, t, b);
    }
    __syncthreads();
    { float2* tp = src; src = dst; dst = tp; }
#pragma unroll
    for (int ls = 3; ls <= 9; ls += 3) {
        radix8_mid<true>(src, dst, tw8, ls);
        __syncthreads();
        float2* tp = src; src = dst; dst = tp;
    }
    // src holds S2; y[n] = S2[n] + S2[n+4096] for n < 4096 (twiddle = 1).
    const float h0v = h0p[0];
    float2* y1row = reinterpret_cast<float2*>(g_y1 + (size_t)r * kSeq);
    for (int n = t; n < 4096; n += 1024) {
        float2 v = cadd(src[SWZ(n)], src[SWZ(n + 4096)]);
        float2 e = row2[n];
        y1row[n] = make_float2(gelu_exact(v.x + h0v * e.x),
                               gelu_exact(v.y + h0v * e.y));
    }
}

__global__ void hout_kernel(float* __restrict__ h) {
    int i = blockIdx.x * 256 + threadIdx.x;
    if (i < kB * kCh)
        h[i] = __uint_as_float(g_maxy[i]) / (__uint_as_float(g_maxxe[i]) + 1e-6f);
}

extern "C" void kernel_launch(void* const* d_in, const int* in_sizes, int n_in,
                              void* d_out, int out_size) {
    const float* x     = (const float*)d_in[0];
    const float* A     = (const float*)d_in[1];
    const float* Bp    = (const float*)d_in[2];
    const float* h0    = (const float*)d_in[3];
    const float* W_enc = (const float*)d_in[4];
    const float* b_enc = (const float*)d_in[5];
    const float* W_fc  = (const float*)d_in[6];
    const float* b_fc  = (const float*)d_in[7];
    const float* gamma = (const float*)d_in[8];
    const float* beta  = (const float*)d_in[9];
    const float* W_dec = (const float*)d_in[10];
    const float* b_dec = (const float*)d_in[11];
    float* out = (float*)d_out;

    static cudaStream_t side = nullptr;
    static cudaEvent_t evFork = nullptr, evJoin = nullptr;
    static bool attrsSet = false;
    if (!side) {
        cudaStreamCreateWithFlags(&side, cudaStreamNonBlocking);
        cudaEventCreateWithFlags(&evFork, cudaEventDisableTiming);
        cudaEventCreateWithFlags(&evJoin, cudaEventDisableTiming);
    }
    const int kSmemFFT = 24578 * 8;   // 196624 B dynamic SMEM
    if (!attrsSet) {
        cudaFuncSetAttribute(fftconv_kernel, cudaFuncAttributeMaxDynamicSharedMemorySize, kSmemFFT);
        cudaFuncSetAttribute(gemm_kernel<0>, cudaFuncAttributeMaxDynamicSharedMemorySize, kGemmSmem);
        cudaFuncSetAttribute(gemm_kernel<1>, cudaFuncAttributeMaxDynamicSharedMemorySize, kGemmSmem);
        cudaFuncSetAttribute(gemm_kernel<2>, cudaFuncAttributeMaxDynamicSharedMemorySize, kGemmSmem);
        attrsSet = true;
    }

    cudaEventRecord(evFork, 0);
    cudaStreamWaitEvent(side, evFork, 0);
    twiddle_kernel<<<17, 256, 0, side>>>();
    kfgen_kernel<<<dim3(33, kCh), 256, 0, side>>>(A, Bp);
    cudaEventRecord(evJoin, side);

    zero_kernel<<<8, 256>>>();
    wsplit_kernel<<<dim3(kCh * kCh / 256, 3), 256>>>(W_enc, W_fc, W_dec);
    gemm_kernel<0><<<dim3(kM / 128, 2), 256, kGemmSmem>>>(x, b_enc, nullptr, nullptr, nullptr);
    cudaStreamWaitEvent(0, evJoin, 0);
    fftconv_kernel<<<kB * kCh, 1024, kSmemFFT>>>(h0);
    gemm_kernel<1><<<dim3(kM / 128, 2), 256, kGemmSmem>>>(nullptr, b_fc, nullptr, nullptr, nullptr);
    lnstats_kernel<<<kM / 256, 256>>>();
    gemm_kernel<2><<<dim3(kM / 128, 2), 256, kGemmSmem>>>(nullptr, b_dec, out, gamma, beta);
    hout_kernel<<<8, 256>>>(out + (size_t)kM * kCh);
}